// round 15
// baseline (speedup 1.0000x reference)
#include <cuda_runtime.h>
#include <cuda_bf16.h>

#define LNUM 2
#define BB 64
#define TSTEPS 512
#define DIN 512
#define HD 512
#define PD 256
#define OD 512
#define NBLK 148
#define NTHR 256

// ----------------- persistent device state (no allocations) -----------------
__device__ float g_h[LNUM][BB * HD];    // h_mem per layer
__device__ float g_m[LNUM][BB * PD];    // memory per layer
__device__ float g_rh[BB * HD];         // sigma(r) * h_old   (current layer)
__device__ float g_us[BB * HD];         // sigma(u)           (current layer)
__device__ float g_hc[BB * HD];         // h_cand             (current layer)
__device__ float g_pr[4][BB * HD];      // r preact partials (split-4)
__device__ float g_pu[4][BB * HD];      // u preact partials (split-4)
__device__ float g_pn[6][BB * HD];      // n partials: 2 x-half + 4 rh-half
__device__ float g_pmr[4][BB * PD];     // read-gate preact partials (split-4)
__device__ float g_pwg[4][2][BB * PD];  // write-gate raw partials: mw,mu,d,s x split-2
__device__ float g_po[2][BB * OD];      // output raw partials (split-2)
__device__ unsigned g_flags[NBLK * 32]; // per-block arrival flags (128B stride)
__device__ unsigned g_gen2;             // published generation

struct Params {
    const float *x, *Wr, *br, *Wu, *bu, *Wn, *bn, *Wmr, *bmr, *Wmw, *bmw,
                *Wmu, *bmu, *Wmh, *bmh, *Wd, *bd, *Ws, *bs, *Wout, *bout,
                *dop, *ser;
    float* out;
    long long out_size;
};

__device__ __forceinline__ float sigf(float v) { return 1.f / (1.f + __expf(-v)); }
__device__ __forceinline__ float tanhf_(float v) {
    float e = __expf(-2.f * fabsf(v));
    float r = (1.f - e) / (1.f + e);
    return v < 0.f ? -r : r;
}

// Flag-array grid barrier: parallel arrivals, block 0 aggregates, publishes gen.
__device__ __forceinline__ void gridbar(unsigned target) {
    __syncthreads();
    if (blockIdx.x == 0) {
        const int tid = threadIdx.x;
        if (tid >= 1 && tid < NBLK) {
            while (*(volatile unsigned*)&g_flags[tid * 32] != target) { }
            __threadfence();  // acquire other blocks' writes
        }
        __syncthreads();
        if (tid == 0) {
            __threadfence();
            *(volatile unsigned*)&g_gen2 = target;
        }
    } else {
        if (threadIdx.x == 0) {
            __threadfence();  // release this block's writes
            *(volatile unsigned*)&g_flags[blockIdx.x * 32] = target;
            while (*(volatile unsigned*)&g_gen2 != target) { }
            __threadfence();  // acquire
        }
    }
    __syncthreads();
}

struct alignas(16) SM {
    float A[2][32 * 65];  // [k][row], stride 65 -> conflict-free
    float W[2][32 * 36];  // [k][col], stride 36 -> aligned 16B vector reads
};

// C[64, 32] += A[64, 32*nch] * W[32, 32*nch]^T.
// A pre-offset to its k-window; Wp pre-offset to (c0, k0).
// Thread map: row = tid&63, colgroup = tid>>6 (8 cols/thread).
__device__ __forceinline__ void gemm_tile(
    SM& sm, const float* __restrict__ A, long lda,
    const float* __restrict__ Wp, int wstr, int nch, float accf[8])
{
    const int tid = threadIdx.x;
    const int kq = tid & 31;
    const int rq = tid >> 5;   // 0..7
    const int row = tid & 63;
    const int cg = tid >> 6;   // 0..3
    float ra[8], rw[4];
    unsigned long long acc2[4] = {0ull, 0ull, 0ull, 0ull};

    // prologue: chunk 0
#pragma unroll
    for (int i = 0; i < 8; i++) ra[i] = A[(long)(rq + 8 * i) * lda + kq];
#pragma unroll
    for (int i = 0; i < 4; i++) rw[i] = Wp[(size_t)(rq + 8 * i) * wstr + kq];
#pragma unroll
    for (int i = 0; i < 8; i++) sm.A[0][kq * 65 + rq + 8 * i] = ra[i];
#pragma unroll
    for (int i = 0; i < 4; i++) sm.W[0][kq * 36 + rq + 8 * i] = rw[i];

#pragma unroll 1
    for (int ch = 0; ch < nch; ch++) {
        __syncthreads();
        const bool more = (ch + 1 < nch);
        if (more) {
            int kb = ((ch + 1) << 5) + kq;
#pragma unroll
            for (int i = 0; i < 8; i++) ra[i] = A[(long)(rq + 8 * i) * lda + kb];
#pragma unroll
            for (int i = 0; i < 4; i++) rw[i] = Wp[(size_t)(rq + 8 * i) * wstr + kb];
        }
        const int b = ch & 1;
        const float* as = &sm.A[b][row];
        const float* ws = &sm.W[b][cg * 8];
#pragma unroll
        for (int k = 0; k < 32; k++) {
            float a = as[k * 65];
            unsigned long long aa;
            asm("mov.b64 %0, {%1, %1};" : "=l"(aa) : "f"(a));
            ulonglong2 w01 = *(const ulonglong2*)(ws + k * 36);
            ulonglong2 w23 = *(const ulonglong2*)(ws + k * 36 + 4);
            asm("fma.rn.f32x2 %0, %1, %2, %0;" : "+l"(acc2[0]) : "l"(aa), "l"(w01.x));
            asm("fma.rn.f32x2 %0, %1, %2, %0;" : "+l"(acc2[1]) : "l"(aa), "l"(w01.y));
            asm("fma.rn.f32x2 %0, %1, %2, %0;" : "+l"(acc2[2]) : "l"(aa), "l"(w23.x));
            asm("fma.rn.f32x2 %0, %1, %2, %0;" : "+l"(acc2[3]) : "l"(aa), "l"(w23.y));
        }
        if (more) {
            const int nb = (ch + 1) & 1;
#pragma unroll
            for (int i = 0; i < 8; i++) sm.A[nb][kq * 65 + rq + 8 * i] = ra[i];
#pragma unroll
            for (int i = 0; i < 4; i++) sm.W[nb][kq * 36 + rq + 8 * i] = rw[i];
        }
    }
    __syncthreads();
#pragma unroll
    for (int j = 0; j < 4; j++)
        asm("mov.b64 {%0, %1}, %2;"
            : "=f"(accf[2 * j]), "=f"(accf[2 * j + 1]) : "l"(acc2[j]));
}

// Variant for the Wmh GEMM: stages A = mo = sigma(sum(g_pmr)+bmr)*g_m[l]
// inline (recomputed exactly as ew_mo did), K=256 fixed (8 chunks).
__device__ __forceinline__ float mo_of(int l, int r, int k) {
    // caller guarantees k in [0,256)
    extern __device__ float g_pmr[4][BB * PD];
    int idx = r * PD + k;
    return g_pmr[0][idx];  // placeholder (never used; see gemm_tile_mo)
}

__device__ __forceinline__ void gemm_tile_mo(
    SM& sm, int l, const Params& pr,
    const float* __restrict__ Wp, float accf[8])
{
    const int tid = threadIdx.x;
    const int kq = tid & 31;
    const int rq = tid >> 5;   // 0..7
    const int row = tid & 63;
    const int cg = tid >> 6;   // 0..3
    float ra[8], rw[4];
    unsigned long long acc2[4] = {0ull, 0ull, 0ull, 0ull};
    const float* bmr = pr.bmr + l * PD;
    const float* mlp = g_m[l];

    auto stage_a = [&](int kb) {
#pragma unroll
        for (int i = 0; i < 8; i++) {
            int r = rq + 8 * i;
            int idx = r * PD + kb;
            float mr = g_pmr[0][idx] + g_pmr[1][idx] + g_pmr[2][idx]
                       + g_pmr[3][idx] + bmr[kb];
            ra[i] = sigf(mr) * mlp[idx];
        }
    };

    // prologue: chunk 0
    stage_a(kq);
#pragma unroll
    for (int i = 0; i < 4; i++) rw[i] = Wp[(size_t)(rq + 8 * i) * PD + kq];
#pragma unroll
    for (int i = 0; i < 8; i++) sm.A[0][kq * 65 + rq + 8 * i] = ra[i];
#pragma unroll
    for (int i = 0; i < 4; i++) sm.W[0][kq * 36 + rq + 8 * i] = rw[i];

#pragma unroll 1
    for (int ch = 0; ch < 8; ch++) {
        __syncthreads();
        const bool more = (ch < 7);
        if (more) {
            int kb = ((ch + 1) << 5) + kq;
            stage_a(kb);
#pragma unroll
            for (int i = 0; i < 4; i++) rw[i] = Wp[(size_t)(rq + 8 * i) * PD + kb];
        }
        const int b = ch & 1;
        const float* as = &sm.A[b][row];
        const float* ws = &sm.W[b][cg * 8];
#pragma unroll
        for (int k = 0; k < 32; k++) {
            float a = as[k * 65];
            unsigned long long aa;
            asm("mov.b64 %0, {%1, %1};" : "=l"(aa) : "f"(a));
            ulonglong2 w01 = *(const ulonglong2*)(ws + k * 36);
            ulonglong2 w23 = *(const ulonglong2*)(ws + k * 36 + 4);
            asm("fma.rn.f32x2 %0, %1, %2, %0;" : "+l"(acc2[0]) : "l"(aa), "l"(w01.x));
            asm("fma.rn.f32x2 %0, %1, %2, %0;" : "+l"(acc2[1]) : "l"(aa), "l"(w01.y));
            asm("fma.rn.f32x2 %0, %1, %2, %0;" : "+l"(acc2[2]) : "l"(aa), "l"(w23.x));
            asm("fma.rn.f32x2 %0, %1, %2, %0;" : "+l"(acc2[3]) : "l"(aa), "l"(w23.y));
        }
        if (more) {
            const int nb = (ch + 1) & 1;
#pragma unroll
            for (int i = 0; i < 8; i++) sm.A[nb][kq * 65 + rq + 8 * i] = ra[i];
#pragma unroll
            for (int i = 0; i < 4; i++) sm.W[nb][kq * 36 + rq + 8 * i] = rw[i];
        }
    }
    __syncthreads();
#pragma unroll
    for (int j = 0; j < 4; j++)
        asm("mov.b64 {%0, %1}, %2;"
            : "=f"(accf[2 * j]), "=f"(accf[2 * j + 1]) : "l"(acc2[j]));
}

__device__ __forceinline__ void store_part(float* __restrict__ part, int N,
                                           int c0, const float* accf) {
    const int row = threadIdx.x & 63, cg = threadIdx.x >> 6;
    float4* p = (float4*)(part + (size_t)row * N + c0 + cg * 8);
    p[0] = make_float4(accf[0], accf[1], accf[2], accf[3]);
    p[1] = make_float4(accf[4], accf[5], accf[6], accf[7]);
}

__device__ __forceinline__ const float* wgW(const Params& pr, int g) {
    return (g == 0) ? pr.Wmw : (g == 1) ? pr.Wmu : (g == 2) ? pr.Wd : pr.Ws;
}

// elementwise: materialize sigma(r)*h and sigma(u) from split-4 partials
__device__ __forceinline__ void ew_ru(int l, int e, const Params& pr) {
    const int tid = threadIdx.x;
#pragma unroll
    for (int j = 0; j < 8; j++) {
        int i = e * 2048 + j * 256 + tid;
        int c = i & 511;
        float rr = g_pr[0][i] + g_pr[1][i] + g_pr[2][i] + g_pr[3][i]
                   + pr.br[l * HD + c];
        g_rh[i] = sigf(rr) * g_h[l][i];
        float uu = g_pu[0][i] + g_pu[1][i] + g_pu[2][i] + g_pu[3][i]
                   + pr.bu[l * HD + c];
        g_us[i] = sigf(uu);
    }
}

// elementwise: materialize h_cand from n partials (6-way) + sigma(u)
__device__ __forceinline__ void ew_hc(int l, int e, const Params& pr) {
    const int tid = threadIdx.x;
#pragma unroll
    for (int j = 0; j < 8; j++) {
        int i = e * 2048 + j * 256 + tid;
        int c = i & 511;
        float nn = g_pn[0][i] + g_pn[1][i] + g_pn[2][i] + g_pn[3][i]
                   + g_pn[4][i] + g_pn[5][i] + pr.bn[l * HD + c];
        float u = g_us[i];
        g_hc[i] = (1.f - u) * g_h[l][i] + u * tanhf_(nn);
    }
}

// elementwise: apply memory update for layer l from raw write-gate partials
__device__ __forceinline__ void ec_m(int l, int e, const Params& pr,
                                     float dopa, float sero) {
    const int tid = threadIdx.x;
#pragma unroll
    for (int j = 0; j < 8; j++) {
        int i = e * 2048 + j * 256 + tid;
        int c = i & 255;
        float wmw = g_pwg[0][0][i] + g_pwg[0][1][i] + pr.bmw[l * PD + c];
        float wmu = g_pwg[1][0][i] + g_pwg[1][1][i] + pr.bmu[l * PD + c];
        float wd  = g_pwg[2][0][i] + g_pwg[2][1][i] + pr.bd[l * PD + c];
        float wsv = g_pwg[3][0][i] + g_pwg[3][1][i] + pr.bs[l * PD + c];
        float w = sigf(wmw) * sigf(wd * dopa) * (1.f - sigf(wsv * sero));
        g_m[l][i] = (1.f - w) * g_m[l][i] + w * tanhf_(wmu);
    }
}

__device__ __forceinline__ void ec_out(int tprev, int e, const Params& pr) {
    const int tid = threadIdx.x;
#pragma unroll
    for (int j = 0; j < 8; j++) {
        int i = e * 2048 + j * 256 + tid;
        int r = i >> 9, c = i & 511;
        pr.out[((size_t)r * TSTEPS + tprev) * OD + c] =
            g_po[0][i] + g_po[1][i] + pr.bout[c];
    }
}

__global__ void __launch_bounds__(NTHR, 1)
gru_kernel(Params pr)
{
    __shared__ SM sm;
    const int tid = threadIdx.x;
    const int row = tid & 63;
    const int cg = tid >> 6;
    const float dopa = pr.dop[0];
    const float sero = pr.ser[0];
    unsigned bt = 0;  // barrier target (uniform across blocks)

    for (int i = blockIdx.x * NTHR + tid; i < LNUM * BB * HD; i += NBLK * NTHR)
        (&g_h[0][0])[i] = 0.f;
    for (int i = blockIdx.x * NTHR + tid; i < LNUM * BB * PD; i += NBLK * NTHR)
        (&g_m[0][0])[i] = 0.f;
    gridbar(++bt);

    const long LDX = (long)TSTEPS * DIN;  // batch-row stride of x

    for (int t = 0; t < TSTEPS; t++) {
        const float* xt = pr.x + (size_t)t * DIN;
        float acc[8];

        for (int l = 0; l < LNUM; l++) {
            // ---- A: r,u split-4 (128 tiles, 8 chunks each) ----
            for (int tile = blockIdx.x; tile < 128; tile += NBLK) {
                int which = tile >> 6, q = tile & 63;
                int c0 = (q >> 2) * 32, s = q & 3, k0 = s * 256;
                const float* A; long lda;
                if (l == 0) {
                    if (s < 2) { A = xt + k0; lda = LDX; }
                    else       { A = g_h[0] + (k0 - 512); lda = HD; }
                } else {
                    if (s < 2) { A = g_h[0] + k0; lda = HD; }
                    else       { A = g_h[1] + (k0 - 512); lda = HD; }
                }
                const float* W = (which ? pr.Wu : pr.Wr)
                                 + (size_t)(l * HD + c0) * (DIN + HD) + k0;
                gemm_tile(sm, A, lda, W, DIN + HD, 8, acc);
                store_part((which ? g_pu : g_pr)[s], HD, c0, acc);
            }
            gridbar(++bt);

            // ---- B: ew_ru (16) + n-firsthalf split-2 (32)
            //         + [l==0,t>0: out(t-1) split-2 (32)]
            //         + [wg of other layer, split-2 (64)] ----
            {
                int ntB = (l == 0) ? (t ? 144 : 48) : 112;
                int wgbase = (l == 0) ? 80 : 48;
                for (int tile = blockIdx.x; tile < ntB; tile += NBLK) {
                    if (tile < 16) {
                        ew_ru(l, tile, pr);
                    } else if (tile < 48) {  // n first half (x-part / h0-part)
                        int q = tile - 16;
                        int c0 = (q >> 1) * 32, s = q & 1, k0 = s * 256;
                        const float* A; long lda;
                        if (l == 0) { A = xt + k0; lda = LDX; }
                        else        { A = g_h[0] + k0; lda = HD; }
                        const float* W = pr.Wn
                            + (size_t)(l * HD + c0) * (DIN + HD) + k0;
                        gemm_tile(sm, A, lda, W, DIN + HD, 8, acc);
                        store_part(g_pn[s], HD, c0, acc);
                    } else if (l == 0 && tile < 80) {  // out(t-1) from h1(t-1)
                        int q = tile - 48;
                        int c0 = (q >> 1) * 32, s = q & 1;
                        gemm_tile(sm, g_h[1] + s * 256, HD,
                                  pr.Wout + (size_t)c0 * HD + s * 256, HD, 8,
                                  acc);
                        store_part(g_po[s], OD, c0, acc);
                    } else {  // write gates of layer lw
                        int lw = 1 - l;
                        int q = tile - wgbase, g = q >> 4, r2 = q & 15;
                        int c0 = (r2 >> 1) * 32, s = r2 & 1;
                        gemm_tile(sm, g_h[lw] + s * 256, HD,
                                  wgW(pr, g) + (size_t)(lw * PD + c0) * HD
                                      + s * 256,
                                  HD, 8, acc);
                        store_part(g_pwg[g][s], PD, c0, acc);
                    }
                }
            }
            gridbar(++bt);

            // ---- C: n-secondhalf split-4 (64 tiles, 4 chunks)
            //         + [l==0,t>0: ec_m(1) (8) + ec_out(t-1) (16)]
            //         + [l==1: ec_m(0) (8)] ----
            {
                int ntC = (l == 0) ? (t ? 88 : 64) : 72;
                for (int tile = blockIdx.x; tile < ntC; tile += NBLK) {
                    if (tile < 64) {
                        int c0 = (tile >> 2) * 32, s = tile & 3, k0 = s * 128;
                        const float* W = pr.Wn
                            + (size_t)(l * HD + c0) * (DIN + HD) + DIN + k0;
                        gemm_tile(sm, g_rh + k0, HD, W, DIN + HD, 4, acc);
                        store_part(g_pn[2 + s], HD, c0, acc);
                    } else if (tile < 72) {
                        ec_m(1 - l, tile - 64, pr, dopa, sero);
                    } else {
                        ec_out(t - 1, tile - 72, pr);
                    }
                }
            }
            gridbar(++bt);

            // ---- D: materialize h_cand (16 tiles) ----
            for (int tile = blockIdx.x; tile < 16; tile += NBLK)
                ew_hc(l, tile, pr);
            gridbar(++bt);

            // ---- E: read gate split-4 (32 tiles, 4 chunks each) ----
            for (int tile = blockIdx.x; tile < 32; tile += NBLK) {
                int c0 = (tile >> 2) * 32, s = tile & 3, k0 = s * 128;
                gemm_tile(sm, g_hc + k0, HD,
                          pr.Wmr + (size_t)(l * PD + c0) * HD + k0, HD, 4, acc);
                store_part(g_pmr[s], PD, c0, acc);
            }
            gridbar(++bt);

            // ---- F: h_mem = hc + Wmh*mo + bmh; mo recomputed in staging
            //         (16 tiles, 8 chunks, K=256, direct epilogue) ----
            for (int tile = blockIdx.x; tile < 16; tile += NBLK) {
                int c0 = tile * 32;
                gemm_tile_mo(sm, l, pr,
                             pr.Wmh + (size_t)(l * HD + c0) * PD, acc);
#pragma unroll
                for (int j = 0; j < 8; j++) {
                    int c = c0 + cg * 8 + j;
                    int idx = row * HD + c;
                    g_h[l][idx] = g_hc[idx] + acc[j] + pr.bmh[l * HD + c];
                }
            }
            gridbar(++bt);
        }
    }

    // ---- PF1: out(T-1) split-2 (32) + layer-1 write gates split-2 (64) ----
    {
        float acc[8];
        for (int tile = blockIdx.x; tile < 96; tile += NBLK) {
            if (tile < 32) {
                int c0 = (tile >> 1) * 32, s = tile & 1;
                gemm_tile(sm, g_h[1] + s * 256, HD,
                          pr.Wout + (size_t)c0 * HD + s * 256, HD, 8, acc);
                store_part(g_po[s], OD, c0, acc);
            } else {
                int q = tile - 32, g = q >> 4, r2 = q & 15;
                int c0 = (r2 >> 1) * 32, s = r2 & 1;
                gemm_tile(sm, g_h[1] + s * 256, HD,
                          wgW(pr, g) + (size_t)(PD + c0) * HD + s * 256,
                          HD, 8, acc);
                store_part(g_pwg[g][s], PD, c0, acc);
            }
        }
    }
    gridbar(++bt);

    // ---- PF2: final out-combine (16) + m1-combine (8) ----
    for (int tile = blockIdx.x; tile < 24; tile += NBLK) {
        if (tile < 16) ec_out(TSTEPS - 1, tile, pr);
        else           ec_m(1, tile - 16, pr, dopa, sero);
    }
    gridbar(++bt);

    // ---- PF3: h_final, m_final (guarded by out_size) ----
    {
        long long base_h = (long long)BB * TSTEPS * OD;
        long long base_m = base_h + (long long)LNUM * BB * HD;
        const float* hp = &g_h[0][0];
        for (int i = blockIdx.x * NTHR + tid; i < LNUM * BB * HD; i += NBLK * NTHR)
            if (base_h + i < pr.out_size) pr.out[base_h + i] = hp[i];
        const float* mp = &g_m[0][0];
        for (int i = blockIdx.x * NTHR + tid; i < LNUM * BB * PD; i += NBLK * NTHR)
            if (base_m + i < pr.out_size) pr.out[base_m + i] = mp[i];
    }
}

extern "C" void kernel_launch(void* const* d_in, const int* in_sizes, int n_in,
                              void* d_out, int out_size) {
    Params p;
    p.x    = (const float*)d_in[0];
    p.Wr   = (const float*)d_in[1];
    p.br   = (const float*)d_in[2];
    p.Wu   = (const float*)d_in[3];
    p.bu   = (const float*)d_in[4];
    p.Wn   = (const float*)d_in[5];
    p.bn   = (const float*)d_in[6];
    p.Wmr  = (const float*)d_in[7];
    p.bmr  = (const float*)d_in[8];
    p.Wmw  = (const float*)d_in[9];
    p.bmw  = (const float*)d_in[10];
    p.Wmu  = (const float*)d_in[11];
    p.bmu  = (const float*)d_in[12];
    p.Wmh  = (const float*)d_in[13];
    p.bmh  = (const float*)d_in[14];
    p.Wd   = (const float*)d_in[15];
    p.bd   = (const float*)d_in[16];
    p.Ws   = (const float*)d_in[17];
    p.bs   = (const float*)d_in[18];
    p.Wout = (const float*)d_in[19];
    p.bout = (const float*)d_in[20];
    p.dop  = (const float*)d_in[21];
    p.ser  = (const float*)d_in[22];
    p.out  = (float*)d_out;
    p.out_size = (long long)out_size;
    gru_kernel<<<NBLK, NTHR>>>(p);
}

// round 16
// speedup vs baseline: 1.5075x; 1.5075x over previous
#include <cuda_runtime.h>
#include <cuda_bf16.h>

#define LNUM 2
#define BB 64
#define TSTEPS 512
#define DIN 512
#define HD 512
#define PD 256
#define OD 512
#define NBLK 148
#define NTHR 256

// ----------------- persistent device state (no allocations) -----------------
__device__ float g_h[LNUM][BB * HD];    // h_mem per layer
__device__ float g_m[LNUM][BB * PD];    // memory per layer
__device__ float g_rh[BB * HD];         // sigma(r) * h_old   (current layer)
__device__ float g_us[BB * HD];         // sigma(u)           (current layer)
__device__ float g_hc[BB * HD];         // h_cand             (current layer)
__device__ float g_mo[BB * PD];         // read_gate * m      (current layer)
__device__ float g_pr[4][BB * HD];      // r preact partials (split-4)
__device__ float g_pu[4][BB * HD];      // u preact partials (split-4)
__device__ float g_pn[6][BB * HD];      // n partials: 2 x-half + 4 rh-half
__device__ float g_pmr[4][BB * PD];     // read-gate preact partials (split-4)
__device__ float g_pf[2][BB * HD];      // Wmh gemm partials (split-2)
__device__ float g_pwg[4][2][BB * PD];  // write-gate raw partials: mw,mu,d,s x split-2
__device__ float g_po[2][BB * OD];      // output raw partials (split-2)
__device__ unsigned g_flags[NBLK * 32]; // per-block arrival flags (128B stride)
__device__ unsigned g_genA[32 * 32];    // 32 generation copies (128B stride)

struct Params {
    const float *x, *Wr, *br, *Wu, *bu, *Wn, *bn, *Wmr, *bmr, *Wmw, *bmw,
                *Wmu, *bmu, *Wmh, *bmh, *Wd, *bd, *Ws, *bs, *Wout, *bout,
                *dop, *ser;
    float* out;
    long long out_size;
};

__device__ __forceinline__ float sigf(float v) { return 1.f / (1.f + __expf(-v)); }
__device__ __forceinline__ float tanhf_(float v) {
    float e = __expf(-2.f * fabsf(v));
    float r = (1.f - e) / (1.f + e);
    return v < 0.f ? -r : r;
}

// Flag-array grid barrier with sharded release: parallel arrivals (one flag
// per block), block 0 aggregates, then publishes the generation to 32 copies
// on distinct 128B lines; each block polls copy (bid & 31) -> <=5 pollers per
// line, removing same-line release fan-out serialization.
__device__ __forceinline__ void gridbar(unsigned target) {
    __syncthreads();
    const int tid = threadIdx.x;
    if (blockIdx.x == 0) {
        if (tid >= 1 && tid < NBLK) {
            while (*(volatile unsigned*)&g_flags[tid * 32] != target) { }
            __threadfence();  // acquire other blocks' writes
        }
        __syncthreads();
        if (tid < 32) {
            __threadfence();
            *(volatile unsigned*)&g_genA[tid * 32] = target;
        }
    } else {
        if (tid == 0) {
            __threadfence();  // release this block's writes
            *(volatile unsigned*)&g_flags[blockIdx.x * 32] = target;
            volatile unsigned* gp = &g_genA[(blockIdx.x & 31) * 32];
            while (*gp != target) { }
            __threadfence();  // acquire
        }
    }
    __syncthreads();
}

struct alignas(16) SM {
    float A[2][32 * 65];  // [k][row], stride 65 -> conflict-free
    float W[2][32 * 36];  // [k][col], stride 36 -> aligned 16B vector reads
};

// C[64, 32] += A[64, 32*nch] * W[32, 32*nch]^T.
// A pre-offset to its k-window; Wp pre-offset to (c0, k0).
// Thread map: row = tid&63, colgroup = tid>>6 (8 cols/thread).
__device__ __forceinline__ void gemm_tile(
    SM& sm, const float* __restrict__ A, long lda,
    const float* __restrict__ Wp, int wstr, int nch, float accf[8])
{
    const int tid = threadIdx.x;
    const int kq = tid & 31;
    const int rq = tid >> 5;   // 0..7
    const int row = tid & 63;
    const int cg = tid >> 6;   // 0..3
    float ra[8], rw[4];
    unsigned long long acc2[4] = {0ull, 0ull, 0ull, 0ull};

    // prologue: chunk 0
#pragma unroll
    for (int i = 0; i < 8; i++) ra[i] = A[(long)(rq + 8 * i) * lda + kq];
#pragma unroll
    for (int i = 0; i < 4; i++) rw[i] = Wp[(size_t)(rq + 8 * i) * wstr + kq];
#pragma unroll
    for (int i = 0; i < 8; i++) sm.A[0][kq * 65 + rq + 8 * i] = ra[i];
#pragma unroll
    for (int i = 0; i < 4; i++) sm.W[0][kq * 36 + rq + 8 * i] = rw[i];

#pragma unroll 1
    for (int ch = 0; ch < nch; ch++) {
        __syncthreads();
        const bool more = (ch + 1 < nch);
        if (more) {
            int kb = ((ch + 1) << 5) + kq;
#pragma unroll
            for (int i = 0; i < 8; i++) ra[i] = A[(long)(rq + 8 * i) * lda + kb];
#pragma unroll
            for (int i = 0; i < 4; i++) rw[i] = Wp[(size_t)(rq + 8 * i) * wstr + kb];
        }
        const int b = ch & 1;
        const float* as = &sm.A[b][row];
        const float* ws = &sm.W[b][cg * 8];
#pragma unroll
        for (int k = 0; k < 32; k++) {
            float a = as[k * 65];
            unsigned long long aa;
            asm("mov.b64 %0, {%1, %1};" : "=l"(aa) : "f"(a));
            ulonglong2 w01 = *(const ulonglong2*)(ws + k * 36);
            ulonglong2 w23 = *(const ulonglong2*)(ws + k * 36 + 4);
            asm("fma.rn.f32x2 %0, %1, %2, %0;" : "+l"(acc2[0]) : "l"(aa), "l"(w01.x));
            asm("fma.rn.f32x2 %0, %1, %2, %0;" : "+l"(acc2[1]) : "l"(aa), "l"(w01.y));
            asm("fma.rn.f32x2 %0, %1, %2, %0;" : "+l"(acc2[2]) : "l"(aa), "l"(w23.x));
            asm("fma.rn.f32x2 %0, %1, %2, %0;" : "+l"(acc2[3]) : "l"(aa), "l"(w23.y));
        }
        if (more) {
            const int nb = (ch + 1) & 1;
#pragma unroll
            for (int i = 0; i < 8; i++) sm.A[nb][kq * 65 + rq + 8 * i] = ra[i];
#pragma unroll
            for (int i = 0; i < 4; i++) sm.W[nb][kq * 36 + rq + 8 * i] = rw[i];
        }
    }
    __syncthreads();
#pragma unroll
    for (int j = 0; j < 4; j++)
        asm("mov.b64 {%0, %1}, %2;"
            : "=f"(accf[2 * j]), "=f"(accf[2 * j + 1]) : "l"(acc2[j]));
}

__device__ __forceinline__ void store_part(float* __restrict__ part, int N,
                                           int c0, const float* accf) {
    const int row = threadIdx.x & 63, cg = threadIdx.x >> 6;
    float4* p = (float4*)(part + (size_t)row * N + c0 + cg * 8);
    p[0] = make_float4(accf[0], accf[1], accf[2], accf[3]);
    p[1] = make_float4(accf[4], accf[5], accf[6], accf[7]);
}

__device__ __forceinline__ const float* wgW(const Params& pr, int g) {
    return (g == 0) ? pr.Wmw : (g == 1) ? pr.Wmu : (g == 2) ? pr.Wd : pr.Ws;
}

#define LD4(dst, arr, i4) *(float4*)(dst) = ((const float4*)(arr))[i4]

// elementwise: materialize sigma(r)*h and sigma(u) from split-4 partials
__device__ __forceinline__ void ew_ru(int l, int e, const Params& pr) {
    const int tid = threadIdx.x;
#pragma unroll
    for (int j = 0; j < 2; j++) {
        int i4 = e * 512 + j * 256 + tid;
        int c4 = i4 & 127;
        float p0[4], p1[4], p2[4], p3[4], u0[4], u1[4], u2[4], u3[4];
        float br4[4], bu4[4], hh[4], rh[4], us[4];
        LD4(p0, g_pr[0], i4); LD4(p1, g_pr[1], i4);
        LD4(p2, g_pr[2], i4); LD4(p3, g_pr[3], i4);
        LD4(u0, g_pu[0], i4); LD4(u1, g_pu[1], i4);
        LD4(u2, g_pu[2], i4); LD4(u3, g_pu[3], i4);
        LD4(br4, pr.br + l * HD, c4); LD4(bu4, pr.bu + l * HD, c4);
        LD4(hh, g_h[l], i4);
#pragma unroll
        for (int q = 0; q < 4; q++) {
            float rr = p0[q] + p1[q] + p2[q] + p3[q] + br4[q];
            rh[q] = sigf(rr) * hh[q];
            float uu = u0[q] + u1[q] + u2[q] + u3[q] + bu4[q];
            us[q] = sigf(uu);
        }
        ((float4*)g_rh)[i4] = *(float4*)rh;
        ((float4*)g_us)[i4] = *(float4*)us;
    }
}

// elementwise: materialize h_cand from n partials (6-way) + sigma(u)
__device__ __forceinline__ void ew_hc(int l, int e, const Params& pr) {
    const int tid = threadIdx.x;
#pragma unroll
    for (int j = 0; j < 2; j++) {
        int i4 = e * 512 + j * 256 + tid;
        int c4 = i4 & 127;
        float n0[4], n1[4], n2[4], n3[4], n4[4], n5[4];
        float bn4[4], uu[4], hh[4], hc[4];
        LD4(n0, g_pn[0], i4); LD4(n1, g_pn[1], i4); LD4(n2, g_pn[2], i4);
        LD4(n3, g_pn[3], i4); LD4(n4, g_pn[4], i4); LD4(n5, g_pn[5], i4);
        LD4(bn4, pr.bn + l * HD, c4);
        LD4(uu, g_us, i4); LD4(hh, g_h[l], i4);
#pragma unroll
        for (int q = 0; q < 4; q++) {
            float nn = n0[q] + n1[q] + n2[q] + n3[q] + n4[q] + n5[q] + bn4[q];
            float u = uu[q];
            hc[q] = (1.f - u) * hh[q] + u * tanhf_(nn);
        }
        ((float4*)g_hc)[i4] = *(float4*)hc;
    }
}

// elementwise: materialize mo = sigma(read_gate) * m from split-4 partials
__device__ __forceinline__ void ew_mo(int l, int e, const Params& pr) {
    const int tid = threadIdx.x;
#pragma unroll
    for (int j = 0; j < 2; j++) {
        int i4 = e * 512 + j * 256 + tid;
        int c4 = i4 & 63;
        float p0[4], p1[4], p2[4], p3[4], b4[4], mm[4], mo[4];
        LD4(p0, g_pmr[0], i4); LD4(p1, g_pmr[1], i4);
        LD4(p2, g_pmr[2], i4); LD4(p3, g_pmr[3], i4);
        LD4(b4, pr.bmr + l * PD, c4); LD4(mm, g_m[l], i4);
#pragma unroll
        for (int q = 0; q < 4; q++) {
            float mr = p0[q] + p1[q] + p2[q] + p3[q] + b4[q];
            mo[q] = sigf(mr) * mm[q];
        }
        ((float4*)g_mo)[i4] = *(float4*)mo;
    }
}

// elementwise: h_mem = h_cand + Wmh-partials + bmh
__device__ __forceinline__ void ew_hm(int l, int e, const Params& pr) {
    const int tid = threadIdx.x;
#pragma unroll
    for (int j = 0; j < 2; j++) {
        int i4 = e * 512 + j * 256 + tid;
        int c4 = i4 & 127;
        float hc[4], f0[4], f1[4], b4[4], hh[4];
        LD4(hc, g_hc, i4); LD4(f0, g_pf[0], i4); LD4(f1, g_pf[1], i4);
        LD4(b4, pr.bmh + l * HD, c4);
#pragma unroll
        for (int q = 0; q < 4; q++)
            hh[q] = hc[q] + f0[q] + f1[q] + b4[q];
        ((float4*)g_h[l])[i4] = *(float4*)hh;
    }
}

// elementwise: apply memory update for layer l from raw write-gate partials
__device__ __forceinline__ void ec_m(int l, int e, const Params& pr,
                                     float dopa, float sero) {
    const int tid = threadIdx.x;
#pragma unroll
    for (int j = 0; j < 2; j++) {
        int i4 = e * 512 + j * 256 + tid;
        int c4 = i4 & 63;
        float w00[4], w01[4], w10[4], w11[4], w20[4], w21[4], w30[4], w31[4];
        float bw[4], bu4[4], bd4[4], bs4[4], mm[4], mo[4];
        LD4(w00, g_pwg[0][0], i4); LD4(w01, g_pwg[0][1], i4);
        LD4(w10, g_pwg[1][0], i4); LD4(w11, g_pwg[1][1], i4);
        LD4(w20, g_pwg[2][0], i4); LD4(w21, g_pwg[2][1], i4);
        LD4(w30, g_pwg[3][0], i4); LD4(w31, g_pwg[3][1], i4);
        LD4(bw, pr.bmw + l * PD, c4); LD4(bu4, pr.bmu + l * PD, c4);
        LD4(bd4, pr.bd + l * PD, c4); LD4(bs4, pr.bs + l * PD, c4);
        LD4(mm, g_m[l], i4);
#pragma unroll
        for (int q = 0; q < 4; q++) {
            float wmw = w00[q] + w01[q] + bw[q];
            float wmu = w10[q] + w11[q] + bu4[q];
            float wd  = w20[q] + w21[q] + bd4[q];
            float wsv = w30[q] + w31[q] + bs4[q];
            float w = sigf(wmw) * sigf(wd * dopa) * (1.f - sigf(wsv * sero));
            mo[q] = (1.f - w) * mm[q] + w * tanhf_(wmu);
        }
        ((float4*)g_m[l])[i4] = *(float4*)mo;
    }
}

__device__ __forceinline__ void ec_out(int tprev, int e, const Params& pr) {
    const int tid = threadIdx.x;
#pragma unroll
    for (int j = 0; j < 2; j++) {
        int i4 = e * 512 + j * 256 + tid;
        int r = i4 >> 7, c4 = i4 & 127;
        float p0[4], p1[4], b4[4], o[4];
        LD4(p0, g_po[0], i4); LD4(p1, g_po[1], i4);
        LD4(b4, pr.bout, c4);
#pragma unroll
        for (int q = 0; q < 4; q++)
            o[q] = p0[q] + p1[q] + b4[q];
        ((float4*)pr.out)[((size_t)r * TSTEPS + tprev) * (OD / 4) + c4] =
            *(float4*)o;
    }
}

__global__ void __launch_bounds__(NTHR, 1)
gru_kernel(Params pr)
{
    __shared__ SM sm;
    const int tid = threadIdx.x;
    const float dopa = pr.dop[0];
    const float sero = pr.ser[0];
    unsigned bt = 0;  // barrier target (uniform across blocks)

    for (int i = blockIdx.x * NTHR + tid; i < LNUM * BB * HD; i += NBLK * NTHR)
        (&g_h[0][0])[i] = 0.f;
    for (int i = blockIdx.x * NTHR + tid; i < LNUM * BB * PD; i += NBLK * NTHR)
        (&g_m[0][0])[i] = 0.f;
    gridbar(++bt);

    const long LDX = (long)TSTEPS * DIN;  // batch-row stride of x

    for (int t = 0; t < TSTEPS; t++) {
        const float* xt = pr.x + (size_t)t * DIN;
        float acc[8];

        for (int l = 0; l < LNUM; l++) {
            // ---- A: r,u split-4 (128 tiles, 8 chunks each) ----
            for (int tile = blockIdx.x; tile < 128; tile += NBLK) {
                int which = tile >> 6, q = tile & 63;
                int c0 = (q >> 2) * 32, s = q & 3, k0 = s * 256;
                const float* A; long lda;
                if (l == 0) {
                    if (s < 2) { A = xt + k0; lda = LDX; }
                    else       { A = g_h[0] + (k0 - 512); lda = HD; }
                } else {
                    if (s < 2) { A = g_h[0] + k0; lda = HD; }
                    else       { A = g_h[1] + (k0 - 512); lda = HD; }
                }
                const float* W = (which ? pr.Wu : pr.Wr)
                                 + (size_t)(l * HD + c0) * (DIN + HD) + k0;
                gemm_tile(sm, A, lda, W, DIN + HD, 8, acc);
                store_part((which ? g_pu : g_pr)[s], HD, c0, acc);
            }
            gridbar(++bt);

            // ---- B: ew_ru (16) + n-firsthalf split-2 (32)
            //         + [l==0,t>0: out(t-1) split-2 (32)]
            //         + [wg of other layer, split-2 (64)] ----
            {
                int ntB = (l == 0) ? (t ? 144 : 48) : 112;
                int wgbase = (l == 0) ? 80 : 48;
                for (int tile = blockIdx.x; tile < ntB; tile += NBLK) {
                    if (tile < 16) {
                        ew_ru(l, tile, pr);
                    } else if (tile < 48) {  // n first half (x-part / h0-part)
                        int q = tile - 16;
                        int c0 = (q >> 1) * 32, s = q & 1, k0 = s * 256;
                        const float* A; long lda;
                        if (l == 0) { A = xt + k0; lda = LDX; }
                        else        { A = g_h[0] + k0; lda = HD; }
                        const float* W = pr.Wn
                            + (size_t)(l * HD + c0) * (DIN + HD) + k0;
                        gemm_tile(sm, A, lda, W, DIN + HD, 8, acc);
                        store_part(g_pn[s], HD, c0, acc);
                    } else if (l == 0 && tile < 80) {  // out(t-1) from h1(t-1)
                        int q = tile - 48;
                        int c0 = (q >> 1) * 32, s = q & 1;
                        gemm_tile(sm, g_h[1] + s * 256, HD,
                                  pr.Wout + (size_t)c0 * HD + s * 256, HD, 8,
                                  acc);
                        store_part(g_po[s], OD, c0, acc);
                    } else {  // write gates of layer lw
                        int lw = 1 - l;
                        int q = tile - wgbase, g = q >> 4, r2 = q & 15;
                        int c0 = (r2 >> 1) * 32, s = r2 & 1;
                        gemm_tile(sm, g_h[lw] + s * 256, HD,
                                  wgW(pr, g) + (size_t)(lw * PD + c0) * HD
                                      + s * 256,
                                  HD, 8, acc);
                        store_part(g_pwg[g][s], PD, c0, acc);
                    }
                }
            }
            gridbar(++bt);

            // ---- C: n-secondhalf split-4 (64 tiles, 4 chunks)
            //         + [l==0,t>0: ec_m(1) (8) + ec_out(t-1) (16)]
            //         + [l==1: ec_m(0) (8)] ----
            {
                int ntC = (l == 0) ? (t ? 88 : 64) : 72;
                for (int tile = blockIdx.x; tile < ntC; tile += NBLK) {
                    if (tile < 64) {
                        int c0 = (tile >> 2) * 32, s = tile & 3, k0 = s * 128;
                        const float* W = pr.Wn
                            + (size_t)(l * HD + c0) * (DIN + HD) + DIN + k0;
                        gemm_tile(sm, g_rh + k0, HD, W, DIN + HD, 4, acc);
                        store_part(g_pn[2 + s], HD, c0, acc);
                    } else if (tile < 72) {
                        ec_m(1 - l, tile - 64, pr, dopa, sero);
                    } else {
                        ec_out(t - 1, tile - 72, pr);
                    }
                }
            }
            gridbar(++bt);

            // ---- D: materialize h_cand (16 tiles) ----
            for (int tile = blockIdx.x; tile < 16; tile += NBLK)
                ew_hc(l, tile, pr);
            gridbar(++bt);

            // ---- E: read gate split-4 (32 tiles, 4 chunks each) ----
            for (int tile = blockIdx.x; tile < 32; tile += NBLK) {
                int c0 = (tile >> 2) * 32, s = tile & 3, k0 = s * 128;
                gemm_tile(sm, g_hc + k0, HD,
                          pr.Wmr + (size_t)(l * PD + c0) * HD + k0, HD, 4, acc);
                store_part(g_pmr[s], PD, c0, acc);
            }
            gridbar(++bt);

            // ---- E2: materialize mo (8 tiles) ----
            for (int tile = blockIdx.x; tile < 8; tile += NBLK)
                ew_mo(l, tile, pr);
            gridbar(++bt);

            // ---- F: Wmh gemm split-2 (32 tiles, 4 chunks each) ----
            for (int tile = blockIdx.x; tile < 32; tile += NBLK) {
                int c0 = (tile >> 1) * 32, s = tile & 1, k0 = s * 128;
                gemm_tile(sm, g_mo + k0, PD,
                          pr.Wmh + (size_t)(l * HD + c0) * PD + k0, PD, 4, acc);
                store_part(g_pf[s], HD, c0, acc);
            }
            gridbar(++bt);

            // ---- F2: h_mem = hc + pf + bmh (16 tiles) ----
            for (int tile = blockIdx.x; tile < 16; tile += NBLK)
                ew_hm(l, tile, pr);
            gridbar(++bt);
        }
    }

    // ---- PF1: out(T-1) split-2 (32) + layer-1 write gates split-2 (64) ----
    {
        float acc[8];
        for (int tile = blockIdx.x; tile < 96; tile += NBLK) {
            if (tile < 32) {
                int c0 = (tile >> 1) * 32, s = tile & 1;
                gemm_tile(sm, g_h[1] + s * 256, HD,
                          pr.Wout + (size_t)c0 * HD + s * 256, HD, 8, acc);
                store_part(g_po[s], OD, c0, acc);
            } else {
                int q = tile - 32, g = q >> 4, r2 = q & 15;
                int c0 = (r2 >> 1) * 32, s = r2 & 1;
                gemm_tile(sm, g_h[1] + s * 256, HD,
                          wgW(pr, g) + (size_t)(PD + c0) * HD + s * 256,
                          HD, 8, acc);
                store_part(g_pwg[g][s], PD, c0, acc);
            }
        }
    }
    gridbar(++bt);

    // ---- PF2: final out-combine (16) + m1-combine (8) ----
    for (int tile = blockIdx.x; tile < 24; tile += NBLK) {
        if (tile < 16) ec_out(TSTEPS - 1, tile, pr);
        else           ec_m(1, tile - 16, pr, dopa, sero);
    }
    gridbar(++bt);

    // ---- PF3: h_final, m_final (guarded by out_size) ----
    {
        long long base_h = (long long)BB * TSTEPS * OD;
        long long base_m = base_h + (long long)LNUM * BB * HD;
        const float* hp = &g_h[0][0];
        for (int i = blockIdx.x * NTHR + tid; i < LNUM * BB * HD; i += NBLK * NTHR)
            if (base_h + i < pr.out_size) pr.out[base_h + i] = hp[i];
        const float* mp = &g_m[0][0];
        for (int i = blockIdx.x * NTHR + tid; i < LNUM * BB * PD; i += NBLK * NTHR)
            if (base_m + i < pr.out_size) pr.out[base_m + i] = mp[i];
    }
}

extern "C" void kernel_launch(void* const* d_in, const int* in_sizes, int n_in,
                              void* d_out, int out_size) {
    Params p;
    p.x    = (const float*)d_in[0];
    p.Wr   = (const float*)d_in[1];
    p.br   = (const float*)d_in[2];
    p.Wu   = (const float*)d_in[3];
    p.bu   = (const float*)d_in[4];
    p.Wn   = (const float*)d_in[5];
    p.bn   = (const float*)d_in[6];
    p.Wmr  = (const float*)d_in[7];
    p.bmr  = (const float*)d_in[8];
    p.Wmw  = (const float*)d_in[9];
    p.bmw  = (const float*)d_in[10];
    p.Wmu  = (const float*)d_in[11];
    p.bmu  = (const float*)d_in[12];
    p.Wmh  = (const float*)d_in[13];
    p.bmh  = (const float*)d_in[14];
    p.Wd   = (const float*)d_in[15];
    p.bd   = (const float*)d_in[16];
    p.Ws   = (const float*)d_in[17];
    p.bs   = (const float*)d_in[18];
    p.Wout = (const float*)d_in[19];
    p.bout = (const float*)d_in[20];
    p.dop  = (const float*)d_in[21];
    p.ser  = (const float*)d_in[22];
    p.out  = (float*)d_out;
    p.out_size = (long long)out_size;
    gru_kernel<<<NBLK, NTHR>>>(p);
}

// round 17
// speedup vs baseline: 1.5977x; 1.0598x over previous
#include <cuda_runtime.h>
#include <cuda_bf16.h>

#define LNUM 2
#define BB 64
#define TSTEPS 512
#define DIN 512
#define HD 512
#define PD 256
#define OD 512
#define NBLK 148
#define NTHR 256

// ----------------- persistent device state (no allocations) -----------------
__device__ float g_h[LNUM][BB * HD];    // h_mem per layer
__device__ float g_m[LNUM][BB * PD];    // memory per layer
__device__ float g_rh[BB * HD];         // sigma(r) * h_old   (current layer)
__device__ float g_us[BB * HD];         // sigma(u)           (current layer)
__device__ float g_hc[BB * HD];         // h_cand             (current layer)
__device__ float g_mo[BB * PD];         // read_gate * m      (current layer)
__device__ float g_pr[4][BB * HD];      // r preact partials (split-4)
__device__ float g_pu[4][BB * HD];      // u preact partials (split-4)
__device__ float g_pn[6][BB * HD];      // n partials: 2 x-half + 4 rh-half
__device__ float g_pmr[4][BB * PD];     // read-gate preact partials (split-4)
__device__ float g_pf[2][BB * HD];      // Wmh gemm partials (split-2)
__device__ float g_pwg[4][2][BB * PD];  // write-gate raw partials: mw,mu,d,s x split-2
__device__ float g_po[2][BB * OD];      // output raw partials (split-2)
__device__ unsigned g_flags[NBLK * 32]; // per-block arrival flags (128B stride)
__device__ unsigned g_genA[32 * 32];    // 32 generation copies (128B stride)
__device__ unsigned g_hcf[16 * 32];     // hc-ready flags
__device__ unsigned g_ef[32 * 32];      // E-tile-done flags
__device__ unsigned g_mof[8 * 32];      // mo-ready flags
__device__ unsigned g_ff[32 * 32];      // F-tile-done flags

struct Params {
    const float *x, *Wr, *br, *Wu, *bu, *Wn, *bn, *Wmr, *bmr, *Wmw, *bmw,
                *Wmu, *bmu, *Wmh, *bmh, *Wd, *bd, *Ws, *bs, *Wout, *bout,
                *dop, *ser;
    float* out;
    long long out_size;
};

__device__ __forceinline__ float sigf(float v) { return 1.f / (1.f + __expf(-v)); }
__device__ __forceinline__ float tanhf_(float v) {
    float e = __expf(-2.f * fabsf(v));
    float r = (1.f - e) / (1.f + e);
    return v < 0.f ? -r : r;
}

// Flag-array grid barrier with sharded release (proven in R16).
__device__ __forceinline__ void gridbar(unsigned target) {
    __syncthreads();
    const int tid = threadIdx.x;
    if (blockIdx.x == 0) {
        if (tid >= 1 && tid < NBLK) {
            while (*(volatile unsigned*)&g_flags[tid * 32] != target) { }
            __threadfence();  // acquire other blocks' writes
        }
        __syncthreads();
        if (tid < 32) {
            __threadfence();
            *(volatile unsigned*)&g_genA[tid * 32] = target;
        }
    } else {
        if (tid == 0) {
            __threadfence();  // release this block's writes
            *(volatile unsigned*)&g_flags[blockIdx.x * 32] = target;
            volatile unsigned* gp = &g_genA[(blockIdx.x & 31) * 32];
            while (*gp != target) { }
            __threadfence();  // acquire
        }
    }
    __syncthreads();
}

// Point-to-point flag handoff (same release/acquire pattern as gridbar).
__device__ __forceinline__ void setflag(unsigned* f, unsigned zg) {
    __syncthreads();  // all block threads' data stores complete
    if (threadIdx.x == 0) {
        __threadfence();  // release
        *(volatile unsigned*)f = zg;
    }
}
__device__ __forceinline__ void waitflags(const unsigned* f, int n, unsigned zg) {
    if (threadIdx.x < n) {
        while (*(volatile unsigned*)&f[threadIdx.x * 32] != zg) { }
        __threadfence();  // acquire
    }
    __syncthreads();
}

struct alignas(16) SM {
    float A[2][32 * 65];  // [k][row], stride 65 -> conflict-free
    float W[2][32 * 36];  // [k][col], stride 36 -> aligned 16B vector reads
};

// C[64, 32] += A[64, 32*nch] * W[32, 32*nch]^T.
// A pre-offset to its k-window; Wp pre-offset to (c0, k0).
// Thread map: row = tid&63, colgroup = tid>>6 (8 cols/thread).
__device__ __forceinline__ void gemm_tile(
    SM& sm, const float* __restrict__ A, long lda,
    const float* __restrict__ Wp, int wstr, int nch, float accf[8])
{
    const int tid = threadIdx.x;
    const int kq = tid & 31;
    const int rq = tid >> 5;   // 0..7
    const int row = tid & 63;
    const int cg = tid >> 6;   // 0..3
    float ra[8], rw[4];
    unsigned long long acc2[4] = {0ull, 0ull, 0ull, 0ull};

    // prologue: chunk 0
#pragma unroll
    for (int i = 0; i < 8; i++) ra[i] = A[(long)(rq + 8 * i) * lda + kq];
#pragma unroll
    for (int i = 0; i < 4; i++) rw[i] = Wp[(size_t)(rq + 8 * i) * wstr + kq];
#pragma unroll
    for (int i = 0; i < 8; i++) sm.A[0][kq * 65 + rq + 8 * i] = ra[i];
#pragma unroll
    for (int i = 0; i < 4; i++) sm.W[0][kq * 36 + rq + 8 * i] = rw[i];

#pragma unroll 1
    for (int ch = 0; ch < nch; ch++) {
        __syncthreads();
        const bool more = (ch + 1 < nch);
        if (more) {
            int kb = ((ch + 1) << 5) + kq;
#pragma unroll
            for (int i = 0; i < 8; i++) ra[i] = A[(long)(rq + 8 * i) * lda + kb];
#pragma unroll
            for (int i = 0; i < 4; i++) rw[i] = Wp[(size_t)(rq + 8 * i) * wstr + kb];
        }
        const int b = ch & 1;
        const float* as = &sm.A[b][row];
        const float* ws = &sm.W[b][cg * 8];
#pragma unroll
        for (int k = 0; k < 32; k++) {
            float a = as[k * 65];
            unsigned long long aa;
            asm("mov.b64 %0, {%1, %1};" : "=l"(aa) : "f"(a));
            ulonglong2 w01 = *(const ulonglong2*)(ws + k * 36);
            ulonglong2 w23 = *(const ulonglong2*)(ws + k * 36 + 4);
            asm("fma.rn.f32x2 %0, %1, %2, %0;" : "+l"(acc2[0]) : "l"(aa), "l"(w01.x));
            asm("fma.rn.f32x2 %0, %1, %2, %0;" : "+l"(acc2[1]) : "l"(aa), "l"(w01.y));
            asm("fma.rn.f32x2 %0, %1, %2, %0;" : "+l"(acc2[2]) : "l"(aa), "l"(w23.x));
            asm("fma.rn.f32x2 %0, %1, %2, %0;" : "+l"(acc2[3]) : "l"(aa), "l"(w23.y));
        }
        if (more) {
            const int nb = (ch + 1) & 1;
#pragma unroll
            for (int i = 0; i < 8; i++) sm.A[nb][kq * 65 + rq + 8 * i] = ra[i];
#pragma unroll
            for (int i = 0; i < 4; i++) sm.W[nb][kq * 36 + rq + 8 * i] = rw[i];
        }
    }
    __syncthreads();
#pragma unroll
    for (int j = 0; j < 4; j++)
        asm("mov.b64 {%0, %1}, %2;"
            : "=f"(accf[2 * j]), "=f"(accf[2 * j + 1]) : "l"(acc2[j]));
}

__device__ __forceinline__ void store_part(float* __restrict__ part, int N,
                                           int c0, const float* accf) {
    const int row = threadIdx.x & 63, cg = threadIdx.x >> 6;
    float4* p = (float4*)(part + (size_t)row * N + c0 + cg * 8);
    p[0] = make_float4(accf[0], accf[1], accf[2], accf[3]);
    p[1] = make_float4(accf[4], accf[5], accf[6], accf[7]);
}

__device__ __forceinline__ const float* wgW(const Params& pr, int g) {
    return (g == 0) ? pr.Wmw : (g == 1) ? pr.Wmu : (g == 2) ? pr.Wd : pr.Ws;
}

#define LD4(dst, arr, i4) *(float4*)(dst) = ((const float4*)(arr))[i4]

// elementwise: materialize sigma(r)*h and sigma(u) from split-4 partials
__device__ __forceinline__ void ew_ru(int l, int e, const Params& pr) {
    const int tid = threadIdx.x;
#pragma unroll
    for (int j = 0; j < 2; j++) {
        int i4 = e * 512 + j * 256 + tid;
        int c4 = i4 & 127;
        float p0[4], p1[4], p2[4], p3[4], u0[4], u1[4], u2[4], u3[4];
        float br4[4], bu4[4], hh[4], rh[4], us[4];
        LD4(p0, g_pr[0], i4); LD4(p1, g_pr[1], i4);
        LD4(p2, g_pr[2], i4); LD4(p3, g_pr[3], i4);
        LD4(u0, g_pu[0], i4); LD4(u1, g_pu[1], i4);
        LD4(u2, g_pu[2], i4); LD4(u3, g_pu[3], i4);
        LD4(br4, pr.br + l * HD, c4); LD4(bu4, pr.bu + l * HD, c4);
        LD4(hh, g_h[l], i4);
#pragma unroll
        for (int q = 0; q < 4; q++) {
            float rr = p0[q] + p1[q] + p2[q] + p3[q] + br4[q];
            rh[q] = sigf(rr) * hh[q];
            float uu = u0[q] + u1[q] + u2[q] + u3[q] + bu4[q];
            us[q] = sigf(uu);
        }
        ((float4*)g_rh)[i4] = *(float4*)rh;
        ((float4*)g_us)[i4] = *(float4*)us;
    }
}

// elementwise: materialize h_cand from n partials (6-way) + sigma(u)
__device__ __forceinline__ void ew_hc(int l, int e, const Params& pr) {
    const int tid = threadIdx.x;
#pragma unroll
    for (int j = 0; j < 2; j++) {
        int i4 = e * 512 + j * 256 + tid;
        int c4 = i4 & 127;
        float n0[4], n1[4], n2[4], n3[4], n4[4], n5[4];
        float bn4[4], uu[4], hh[4], hc[4];
        LD4(n0, g_pn[0], i4); LD4(n1, g_pn[1], i4); LD4(n2, g_pn[2], i4);
        LD4(n3, g_pn[3], i4); LD4(n4, g_pn[4], i4); LD4(n5, g_pn[5], i4);
        LD4(bn4, pr.bn + l * HD, c4);
        LD4(uu, g_us, i4); LD4(hh, g_h[l], i4);
#pragma unroll
        for (int q = 0; q < 4; q++) {
            float nn = n0[q] + n1[q] + n2[q] + n3[q] + n4[q] + n5[q] + bn4[q];
            float u = uu[q];
            hc[q] = (1.f - u) * hh[q] + u * tanhf_(nn);
        }
        ((float4*)g_hc)[i4] = *(float4*)hc;
    }
}

// elementwise: materialize mo = sigma(read_gate) * m from split-4 partials
__device__ __forceinline__ void ew_mo(int l, int e, const Params& pr) {
    const int tid = threadIdx.x;
#pragma unroll
    for (int j = 0; j < 2; j++) {
        int i4 = e * 512 + j * 256 + tid;
        int c4 = i4 & 63;
        float p0[4], p1[4], p2[4], p3[4], b4[4], mm[4], mo[4];
        LD4(p0, g_pmr[0], i4); LD4(p1, g_pmr[1], i4);
        LD4(p2, g_pmr[2], i4); LD4(p3, g_pmr[3], i4);
        LD4(b4, pr.bmr + l * PD, c4); LD4(mm, g_m[l], i4);
#pragma unroll
        for (int q = 0; q < 4; q++) {
            float mr = p0[q] + p1[q] + p2[q] + p3[q] + b4[q];
            mo[q] = sigf(mr) * mm[q];
        }
        ((float4*)g_mo)[i4] = *(float4*)mo;
    }
}

// elementwise: h_mem = h_cand + Wmh-partials + bmh
__device__ __forceinline__ void ew_hm(int l, int e, const Params& pr) {
    const int tid = threadIdx.x;
#pragma unroll
    for (int j = 0; j < 2; j++) {
        int i4 = e * 512 + j * 256 + tid;
        int c4 = i4 & 127;
        float hc[4], f0[4], f1[4], b4[4], hh[4];
        LD4(hc, g_hc, i4); LD4(f0, g_pf[0], i4); LD4(f1, g_pf[1], i4);
        LD4(b4, pr.bmh + l * HD, c4);
#pragma unroll
        for (int q = 0; q < 4; q++)
            hh[q] = hc[q] + f0[q] + f1[q] + b4[q];
        ((float4*)g_h[l])[i4] = *(float4*)hh;
    }
}

// elementwise: apply memory update for layer l from raw write-gate partials
__device__ __forceinline__ void ec_m(int l, int e, const Params& pr,
                                     float dopa, float sero) {
    const int tid = threadIdx.x;
#pragma unroll
    for (int j = 0; j < 2; j++) {
        int i4 = e * 512 + j * 256 + tid;
        int c4 = i4 & 63;
        float w00[4], w01[4], w10[4], w11[4], w20[4], w21[4], w30[4], w31[4];
        float bw[4], bu4[4], bd4[4], bs4[4], mm[4], mo[4];
        LD4(w00, g_pwg[0][0], i4); LD4(w01, g_pwg[0][1], i4);
        LD4(w10, g_pwg[1][0], i4); LD4(w11, g_pwg[1][1], i4);
        LD4(w20, g_pwg[2][0], i4); LD4(w21, g_pwg[2][1], i4);
        LD4(w30, g_pwg[3][0], i4); LD4(w31, g_pwg[3][1], i4);
        LD4(bw, pr.bmw + l * PD, c4); LD4(bu4, pr.bmu + l * PD, c4);
        LD4(bd4, pr.bd + l * PD, c4); LD4(bs4, pr.bs + l * PD, c4);
        LD4(mm, g_m[l], i4);
#pragma unroll
        for (int q = 0; q < 4; q++) {
            float wmw = w00[q] + w01[q] + bw[q];
            float wmu = w10[q] + w11[q] + bu4[q];
            float wd  = w20[q] + w21[q] + bd4[q];
            float wsv = w30[q] + w31[q] + bs4[q];
            float w = sigf(wmw) * sigf(wd * dopa) * (1.f - sigf(wsv * sero));
            mo[q] = (1.f - w) * mm[q] + w * tanhf_(wmu);
        }
        ((float4*)g_m[l])[i4] = *(float4*)mo;
    }
}

__device__ __forceinline__ void ec_out(int tprev, int e, const Params& pr) {
    const int tid = threadIdx.x;
#pragma unroll
    for (int j = 0; j < 2; j++) {
        int i4 = e * 512 + j * 256 + tid;
        int r = i4 >> 7, c4 = i4 & 127;
        float p0[4], p1[4], b4[4], o[4];
        LD4(p0, g_po[0], i4); LD4(p1, g_po[1], i4);
        LD4(b4, pr.bout, c4);
#pragma unroll
        for (int q = 0; q < 4; q++)
            o[q] = p0[q] + p1[q] + b4[q];
        ((float4*)pr.out)[((size_t)r * TSTEPS + tprev) * (OD / 4) + c4] =
            *(float4*)o;
    }
}

__global__ void __launch_bounds__(NTHR, 1)
gru_kernel(Params pr)
{
    __shared__ SM sm;
    const int tid = threadIdx.x;
    const float dopa = pr.dop[0];
    const float sero = pr.ser[0];
    unsigned bt = 0;  // barrier target (uniform across blocks)

    for (int i = blockIdx.x * NTHR + tid; i < LNUM * BB * HD; i += NBLK * NTHR)
        (&g_h[0][0])[i] = 0.f;
    for (int i = blockIdx.x * NTHR + tid; i < LNUM * BB * PD; i += NBLK * NTHR)
        (&g_m[0][0])[i] = 0.f;
    gridbar(++bt);

    const long LDX = (long)TSTEPS * DIN;  // batch-row stride of x

    for (int t = 0; t < TSTEPS; t++) {
        const float* xt = pr.x + (size_t)t * DIN;
        float acc[8];

        for (int l = 0; l < LNUM; l++) {
            // ---- A: r,u split-4 (128 tiles, 8 chunks each) ----
            for (int tile = blockIdx.x; tile < 128; tile += NBLK) {
                int which = tile >> 6, q = tile & 63;
                int c0 = (q >> 2) * 32, s = q & 3, k0 = s * 256;
                const float* A; long lda;
                if (l == 0) {
                    if (s < 2) { A = xt + k0; lda = LDX; }
                    else       { A = g_h[0] + (k0 - 512); lda = HD; }
                } else {
                    if (s < 2) { A = g_h[0] + k0; lda = HD; }
                    else       { A = g_h[1] + (k0 - 512); lda = HD; }
                }
                const float* W = (which ? pr.Wu : pr.Wr)
                                 + (size_t)(l * HD + c0) * (DIN + HD) + k0;
                gemm_tile(sm, A, lda, W, DIN + HD, 8, acc);
                store_part((which ? g_pu : g_pr)[s], HD, c0, acc);
            }
            gridbar(++bt);

            // ---- B: ew_ru (16) + n-firsthalf split-2 (32)
            //         + [l==0,t>0: out(t-1) split-2 (32)]
            //         + [wg of other layer, split-2 (64)] ----
            {
                int ntB = (l == 0) ? (t ? 144 : 48) : 112;
                int wgbase = (l == 0) ? 80 : 48;
                for (int tile = blockIdx.x; tile < ntB; tile += NBLK) {
                    if (tile < 16) {
                        ew_ru(l, tile, pr);
                    } else if (tile < 48) {  // n first half (x-part / h0-part)
                        int q = tile - 16;
                        int c0 = (q >> 1) * 32, s = q & 1, k0 = s * 256;
                        const float* A; long lda;
                        if (l == 0) { A = xt + k0; lda = LDX; }
                        else        { A = g_h[0] + k0; lda = HD; }
                        const float* W = pr.Wn
                            + (size_t)(l * HD + c0) * (DIN + HD) + k0;
                        gemm_tile(sm, A, lda, W, DIN + HD, 8, acc);
                        store_part(g_pn[s], HD, c0, acc);
                    } else if (l == 0 && tile < 80) {  // out(t-1) from h1(t-1)
                        int q = tile - 48;
                        int c0 = (q >> 1) * 32, s = q & 1;
                        gemm_tile(sm, g_h[1] + s * 256, HD,
                                  pr.Wout + (size_t)c0 * HD + s * 256, HD, 8,
                                  acc);
                        store_part(g_po[s], OD, c0, acc);
                    } else {  // write gates of layer lw
                        int lw = 1 - l;
                        int q = tile - wgbase, g = q >> 4, r2 = q & 15;
                        int c0 = (r2 >> 1) * 32, s = r2 & 1;
                        gemm_tile(sm, g_h[lw] + s * 256, HD,
                                  wgW(pr, g) + (size_t)(lw * PD + c0) * HD
                                      + s * 256,
                                  HD, 8, acc);
                        store_part(g_pwg[g][s], PD, c0, acc);
                    }
                }
            }
            gridbar(++bt);

            // ---- C: n-secondhalf split-4 (64 tiles, 4 chunks)
            //         + [l==0,t>0: ec_m(1) (8) + ec_out(t-1) (16)]
            //         + [l==1: ec_m(0) (8)] ----
            {
                int ntC = (l == 0) ? (t ? 88 : 64) : 72;
                for (int tile = blockIdx.x; tile < ntC; tile += NBLK) {
                    if (tile < 64) {
                        int c0 = (tile >> 2) * 32, s = tile & 3, k0 = s * 128;
                        const float* W = pr.Wn
                            + (size_t)(l * HD + c0) * (DIN + HD) + DIN + k0;
                        gemm_tile(sm, g_rh + k0, HD, W, DIN + HD, 4, acc);
                        store_part(g_pn[2 + s], HD, c0, acc);
                    } else if (tile < 72) {
                        ec_m(1 - l, tile - 64, pr, dopa, sero);
                    } else {
                        ec_out(t - 1, tile - 72, pr);
                    }
                }
            }
            gridbar(++bt);

            // ---- Z: fused tail chain hc -> mr-GEMM -> mo -> mh-GEMM -> h,
            //         one grid barrier, point-to-point flag handoffs ----
            {
                const unsigned zg = bt + 1;  // unique per phase, monotonic
                const int b = blockIdx.x;
                if (b < 16) {                       // ew_hc
                    ew_hc(l, b, pr);
                    setflag(&g_hcf[b * 32], zg);
                } else if (b < 48) {                // E: read-gate GEMM split-4
                    waitflags(g_hcf, 16, zg);
                    int idx = b - 16;
                    int c0 = (idx >> 2) * 32, s = idx & 3, k0 = s * 128;
                    gemm_tile(sm, g_hc + k0, HD,
                              pr.Wmr + (size_t)(l * PD + c0) * HD + k0, HD, 4,
                              acc);
                    store_part(g_pmr[s], PD, c0, acc);
                    setflag(&g_ef[idx * 32], zg);
                } else if (b < 56) {                // ew_mo
                    waitflags(g_ef, 32, zg);
                    ew_mo(l, b - 48, pr);
                    setflag(&g_mof[(b - 48) * 32], zg);
                } else if (b < 88) {                // F: Wmh GEMM split-2
                    waitflags(g_mof, 8, zg);
                    int idx = b - 56;
                    int c0 = (idx >> 1) * 32, s = idx & 1, k0 = s * 128;
                    gemm_tile(sm, g_mo + k0, PD,
                              pr.Wmh + (size_t)(l * HD + c0) * PD + k0, PD, 4,
                              acc);
                    store_part(g_pf[s], HD, c0, acc);
                    setflag(&g_ff[idx * 32], zg);
                } else if (b < 104) {               // ew_hm -> h_mem
                    waitflags(g_ff, 32, zg);
                    ew_hm(l, b - 88, pr);
                }
                gridbar(++bt);
            }
        }
    }

    // ---- PF1: out(T-1) split-2 (32) + layer-1 write gates split-2 (64) ----
    {
        float acc[8];
        for (int tile = blockIdx.x; tile < 96; tile += NBLK) {
            if (tile < 32) {
                int c0 = (tile >> 1) * 32, s = tile & 1;
                gemm_tile(sm, g_h[1] + s * 256, HD,
                          pr.Wout + (size_t)c0 * HD + s * 256, HD, 8, acc);
                store_part(g_po[s], OD, c0, acc);
            } else {
                int q = tile - 32, g = q >> 4, r2 = q & 15;
                int c0 = (r2 >> 1) * 32, s = r2 & 1;
                gemm_tile(sm, g_h[1] + s * 256, HD,
                          wgW(pr, g) + (size_t)(PD + c0) * HD + s * 256,
                          HD, 8, acc);
                store_part(g_pwg[g][s], PD, c0, acc);
            }
        }
    }
    gridbar(++bt);

    // ---- PF2: final out-combine (16) + m1-combine (8) ----
    for (int tile = blockIdx.x; tile < 24; tile += NBLK) {
        if (tile < 16) ec_out(TSTEPS - 1, tile, pr);
        else           ec_m(1, tile - 16, pr, dopa, sero);
    }
    gridbar(++bt);

    // ---- PF3: h_final, m_final (guarded by out_size) ----
    {
        long long base_h = (long long)BB * TSTEPS * OD;
        long long base_m = base_h + (long long)LNUM * BB * HD;
        const float* hp = &g_h[0][0];
        for (int i = blockIdx.x * NTHR + tid; i < LNUM * BB * HD; i += NBLK * NTHR)
            if (base_h + i < pr.out_size) pr.out[base_h + i] = hp[i];
        const float* mp = &g_m[0][0];
        for (int i = blockIdx.x * NTHR + tid; i < LNUM * BB * PD; i += NBLK * NTHR)
            if (base_m + i < pr.out_size) pr.out[base_m + i] = mp[i];
    }
}

extern "C" void kernel_launch(void* const* d_in, const int* in_sizes, int n_in,
                              void* d_out, int out_size) {
    Params p;
    p.x    = (const float*)d_in[0];
    p.Wr   = (const float*)d_in[1];
    p.br   = (const float*)d_in[2];
    p.Wu   = (const float*)d_in[3];
    p.bu   = (const float*)d_in[4];
    p.Wn   = (const float*)d_in[5];
    p.bn   = (const float*)d_in[6];
    p.Wmr  = (const float*)d_in[7];
    p.bmr  = (const float*)d_in[8];
    p.Wmw  = (const float*)d_in[9];
    p.bmw  = (const float*)d_in[10];
    p.Wmu  = (const float*)d_in[11];
    p.bmu  = (const float*)d_in[12];
    p.Wmh  = (const float*)d_in[13];
    p.bmh  = (const float*)d_in[14];
    p.Wd   = (const float*)d_in[15];
    p.bd   = (const float*)d_in[16];
    p.Ws   = (const float*)d_in[17];
    p.bs   = (const float*)d_in[18];
    p.Wout = (const float*)d_in[19];
    p.bout = (const float*)d_in[20];
    p.dop  = (const float*)d_in[21];
    p.ser  = (const float*)d_in[22];
    p.out  = (float*)d_out;
    p.out_size = (long long)out_size;
    gru_kernel<<<NBLK, NTHR>>>(p);
}